// round 4
// baseline (speedup 1.0000x reference)
#include <cuda_runtime.h>

#define B_ 16
#define N_ 1024
#define D_ 64
#define C_ 64
#define K_ 20
#define EPS_ 0.001f
#define ITERS_ 8
#define HALFD_ 32
#define HALFK_ 10

// scratch (no cudaMalloc allowed)
__device__ int   g_nn_idx[B_ * N_ * K_];
__device__ float g_f0[B_ * N_];

// ---------------------------------------------------------------------------
// packed fp32x2 helpers (sm_103a FFMA2)
// ---------------------------------------------------------------------------
__device__ __forceinline__ unsigned long long pack2(float x, float y) {
    float2 f = make_float2(x, y);
    return *reinterpret_cast<unsigned long long*>(&f);
}
__device__ __forceinline__ float2 unpack2(unsigned long long u) {
    return *reinterpret_cast<float2*>(&u);
}
__device__ __forceinline__ unsigned long long ffma2(unsigned long long a,
                                                    unsigned long long b,
                                                    unsigned long long c) {
    unsigned long long d;
    asm("fma.rn.f32x2 %0, %1, %2, %3;" : "=l"(d) : "l"(a), "l"(b), "l"(c));
    return d;
}

// ---------------------------------------------------------------------------
// Kernel 0: densify f0 = feats[:,:,0]
// ---------------------------------------------------------------------------
__global__ void extract_f0_kernel(const float* __restrict__ feats) {
    int i = blockIdx.x * blockDim.x + threadIdx.x;
    if (i < B_ * N_) g_f0[i] = feats[(size_t)i * D_];
}

// ---------------------------------------------------------------------------
// Kernel 1: exact top-20 smallest of a[j] = adj[b,n,j]*|f0[b,j]-f0[b,n]|.
// Keys unique (index embedded); REDUX-based argmin; tie-break = lowest index,
// matching jax.lax.top_k.
// ---------------------------------------------------------------------------
__global__ void topk_kernel(const float* __restrict__ adj) {
    const int row  = blockIdx.x;            // b*N + n
    const int b    = row >> 10;
    const int tid  = threadIdx.x;           // 256 threads
    const int lane = tid & 31;
    const int wid  = tid >> 5;              // 8 warps

    const float  f0n  = g_f0[row];
    const float* arow = adj + (size_t)row * N_;
    const float* f0b  = g_f0 + b * N_;

    unsigned long long key[4];
#pragma unroll
    for (int t = 0; t < 4; t++) {
        int j = tid + t * 256;
        float a = arow[j] * fabsf(f0b[j] - f0n);
        key[t] = ((unsigned long long)__float_as_uint(a) << 32) | (unsigned)j;
    }
#define CSWP(x, y) { unsigned long long lo = (x) < (y) ? (x) : (y); \
                     unsigned long long hi = (x) < (y) ? (y) : (x); (x) = lo; (y) = hi; }
    CSWP(key[0], key[1]); CSWP(key[2], key[3]);
    CSWP(key[0], key[2]); CSWP(key[1], key[3]);
    CSWP(key[1], key[2]);
#undef CSWP

    __shared__ unsigned long long cand[8][K_];

#pragma unroll 1
    for (int i = 0; i < K_; i++) {
        unsigned v = (unsigned)(key[0] >> 32);
        unsigned m = __reduce_min_sync(0xffffffffu, v);
        unsigned ic = (v == m) ? (unsigned)key[0] : 0xffffffffu;
        unsigned mi = __reduce_min_sync(0xffffffffu, ic);
        if (lane == 0) cand[wid][i] = ((unsigned long long)m << 32) | mi;
        if (v == m && (unsigned)key[0] == mi) {
            key[0] = key[1]; key[1] = key[2]; key[2] = key[3];
            key[3] = ~0ULL;
        }
    }
    __syncthreads();

    if (wid == 0) {
        int q = 0;
        const int out_base = row * K_;
#pragma unroll 1
        for (int i = 0; i < K_; i++) {
            unsigned long long myk = (lane < 8) ? cand[lane][q] : ~0ULL;
            unsigned v = (unsigned)(myk >> 32);
            unsigned m = __reduce_min_sync(0xffffffffu, v);
            unsigned ic = (v == m) ? (unsigned)myk : 0xffffffffu;
            unsigned mi = __reduce_min_sync(0xffffffffu, ic);
            if (lane == 0) g_nn_idx[out_base + i] = (int)mi;
            if (v == m && (unsigned)myk == mi) q++;
        }
    }
}

// ---------------------------------------------------------------------------
// Kernel 2: fused gather + MLP + mean. FFMA2 along reduction dim, reduction
// SPLIT across lane pairs (lane, lane^16): half=lane>>4 owns d/e range
// [half*32, half*32+32); partials combined with one SHFL.BFLY(16) + add.
// Block = 256 threads = 2 groups of 128 (4 warps each); each warp covers 16
// channels x 2 halves. Prefetch of next node's gather overlaps layer-1.
// ---------------------------------------------------------------------------
__global__ void __launch_bounds__(256, 2) edgeconv_kernel(
    const float* __restrict__ feats,
    const float* __restrict__ w1,  const float* __restrict__ b1,
    const float* __restrict__ g1,  const float* __restrict__ be1,
    const float* __restrict__ mu1, const float* __restrict__ v1,
    const float* __restrict__ w2,  const float* __restrict__ b2,
    const float* __restrict__ g2,  const float* __restrict__ be2,
    const float* __restrict__ mu2, const float* __restrict__ v2,
    float* __restrict__ out)
{
    __shared__ __align__(16) float w1c_s[D_ * C_];        // folded w1[0:64,:], [d][c]
    __shared__ __align__(16) float cf[2][2][C_];          // [grp][buf]
    __shared__ __align__(16) float dbuf[2][2][K_][C_];    // [grp][buf][k][d]
    __shared__ __align__(16) float hbuf[2][K_][C_];       // [grp][k][e]

    const int tid  = threadIdx.x;
    const int grp  = tid >> 7;                 // 0/1
    const int gt   = tid & 127;                // thread in group
    const int wig  = gt >> 5;                  // warp-in-group 0..3
    const int lane = tid & 31;
    const int half = lane >> 4;                // 0/1: which reduction half
    const int c    = wig * 16 + (lane & 15);   // owned channel
    const int dbase = half * HALFD_;
    const int kbase = half * HALFK_;
    const int bbase = ((blockIdx.x * (2 * ITERS_)) >> 10) << 10;   // b*N

    const float s1c = g1[c] * rsqrtf(v1[c] + EPS_);
    const float b1f = (b1[c] - mu1[c]) * s1c + be1[c];
    const float s2c = g2[c] * rsqrtf(v2[c] + EPS_);
    const float b2f = (b2[c] - mu2[c]) * s2c + be2[c];

    unsigned long long W1[HALFD_ / 2];   // packed folded w1[64+dbase+2i..+1][c]
    unsigned long long W2[HALFD_ / 2];   // packed folded w2[dbase+2i..+1][c]
#pragma unroll
    for (int i = 0; i < HALFD_ / 2; i++) {
        W1[i] = pack2(w1[(D_ + dbase + 2 * i) * C_ + c] * s1c,
                      w1[(D_ + dbase + 2 * i + 1) * C_ + c] * s1c);
        W2[i] = pack2(w2[(dbase + 2 * i) * C_ + c] * s2c,
                      w2[(dbase + 2 * i + 1) * C_ + c] * s2c);
    }
    // fill center-weight smem (all 256 threads)
    for (int j = tid; j < D_ * C_; j += 256) {
        int cc = j & (C_ - 1);
        w1c_s[j] = w1[j] * (g1[cc] * rsqrtf(v1[cc] + EPS_));
    }

    // gather node i=0 for this group
    {
        const int node0 = blockIdx.x * (2 * ITERS_) + grp;
        const float fc0 = feats[node0 * D_ + c];
        if (half == 0) cf[grp][0][c] = fc0;
        const int* nn = g_nn_idx + node0 * K_ + kbase;
#pragma unroll
        for (int k = 0; k < HALFK_; k++)
            dbuf[grp][0][kbase + k][c] = feats[(bbase + nn[k]) * D_ + c] - fc0;
    }

#pragma unroll 1
    for (int i = 0; i < ITERS_; i++) {
        const int cur  = i & 1, nxt = cur ^ 1;
        const int node = blockIdx.x * (2 * ITERS_) + i * 2 + grp;
        __syncthreads();   // dbuf[cur]/cf[cur] ready; prev hbuf reads done

        // ---- prefetch node i+1 into registers
        float pre[HALFK_];
        float fcn = 0.f;
        if (i < ITERS_ - 1) {
            const int node2 = node + 2;
            const int* nn2  = g_nn_idx + node2 * K_ + kbase;
            fcn = feats[node2 * D_ + c];
#pragma unroll
            for (int k = 0; k < HALFK_; k++)
                pre[k] = feats[(bbase + nn2[k]) * D_ + c];
        }

        // ---- center contribution (this half's 32 d's, then combine)
        float cp0 = 0.f, cp1 = 0.f, cp2 = 0.f, cp3 = 0.f;
#pragma unroll
        for (int d = dbase; d < dbase + HALFD_; d += 4) {
            float4 dv = *(const float4*)&cf[grp][cur][d];
            cp0 += dv.x * w1c_s[(d + 0) * C_ + c];
            cp1 += dv.y * w1c_s[(d + 1) * C_ + c];
            cp2 += dv.z * w1c_s[(d + 2) * C_ + c];
            cp3 += dv.w * w1c_s[(d + 3) * C_ + c];
        }
        float cp = (cp0 + cp1) + (cp2 + cp3);
        cp += __shfl_xor_sync(0xffffffffu, cp, 16);
        const float cpart = cp + b1f;

        // ---- layer 1: all K, packed along d (half range), k-tiled 4
#pragma unroll 1
        for (int t = 0; t < K_; t += 4) {
            unsigned long long A0 = 0, A1 = 0, A2 = 0, A3 = 0;
#pragma unroll
            for (int d = dbase; d < dbase + HALFD_; d += 4) {
                const int w = (d - dbase) >> 1;
                ulonglong2 q0 = *(const ulonglong2*)&dbuf[grp][cur][t + 0][d];
                ulonglong2 q1 = *(const ulonglong2*)&dbuf[grp][cur][t + 1][d];
                ulonglong2 q2 = *(const ulonglong2*)&dbuf[grp][cur][t + 2][d];
                ulonglong2 q3 = *(const ulonglong2*)&dbuf[grp][cur][t + 3][d];
                A0 = ffma2(q0.x, W1[w], A0);  A0 = ffma2(q0.y, W1[w + 1], A0);
                A1 = ffma2(q1.x, W1[w], A1);  A1 = ffma2(q1.y, W1[w + 1], A1);
                A2 = ffma2(q2.x, W1[w], A2);  A2 = ffma2(q2.y, W1[w + 1], A2);
                A3 = ffma2(q3.x, W1[w], A3);  A3 = ffma2(q3.y, W1[w + 1], A3);
            }
            float2 a0 = unpack2(A0), a1 = unpack2(A1), a2 = unpack2(A2), a3 = unpack2(A3);
            float s0 = a0.x + a0.y, s1 = a1.x + a1.y, s2 = a2.x + a2.y, s3 = a3.x + a3.y;
            s0 += __shfl_xor_sync(0xffffffffu, s0, 16);
            s1 += __shfl_xor_sync(0xffffffffu, s1, 16);
            s2 += __shfl_xor_sync(0xffffffffu, s2, 16);
            s3 += __shfl_xor_sync(0xffffffffu, s3, 16);
            if (half == 0) {
                hbuf[grp][t + 0][c] = fmaxf(s0 + cpart, 0.f);
                hbuf[grp][t + 1][c] = fmaxf(s1 + cpart, 0.f);
                hbuf[grp][t + 2][c] = fmaxf(s2 + cpart, 0.f);
                hbuf[grp][t + 3][c] = fmaxf(s3 + cpart, 0.f);
            }
        }

        // ---- store prefetched gather (LDG data has arrived by now)
        if (i < ITERS_ - 1) {
            if (half == 0) cf[grp][nxt][c] = fcn;
#pragma unroll
            for (int k = 0; k < HALFK_; k++)
                dbuf[grp][nxt][kbase + k][c] = pre[k] - fcn;
        }
        __syncthreads();   // hbuf ready; dbuf[nxt] ready

        // ---- layer 2: all K, packed along e (half range), k-tiled 4
        float acc = 0.f;
#pragma unroll 1
        for (int t = 0; t < K_; t += 4) {
            unsigned long long A0 = 0, A1 = 0, A2 = 0, A3 = 0;
#pragma unroll
            for (int e = dbase; e < dbase + HALFD_; e += 4) {
                const int w = (e - dbase) >> 1;
                ulonglong2 q0 = *(const ulonglong2*)&hbuf[grp][t + 0][e];
                ulonglong2 q1 = *(const ulonglong2*)&hbuf[grp][t + 1][e];
                ulonglong2 q2 = *(const ulonglong2*)&hbuf[grp][t + 2][e];
                ulonglong2 q3 = *(const ulonglong2*)&hbuf[grp][t + 3][e];
                A0 = ffma2(q0.x, W2[w], A0);  A0 = ffma2(q0.y, W2[w + 1], A0);
                A1 = ffma2(q1.x, W2[w], A1);  A1 = ffma2(q1.y, W2[w + 1], A1);
                A2 = ffma2(q2.x, W2[w], A2);  A2 = ffma2(q2.y, W2[w + 1], A2);
                A3 = ffma2(q3.x, W2[w], A3);  A3 = ffma2(q3.y, W2[w + 1], A3);
            }
            float2 a0 = unpack2(A0), a1 = unpack2(A1), a2 = unpack2(A2), a3 = unpack2(A3);
            float s0 = a0.x + a0.y, s1 = a1.x + a1.y, s2 = a2.x + a2.y, s3 = a3.x + a3.y;
            s0 += __shfl_xor_sync(0xffffffffu, s0, 16);
            s1 += __shfl_xor_sync(0xffffffffu, s1, 16);
            s2 += __shfl_xor_sync(0xffffffffu, s2, 16);
            s3 += __shfl_xor_sync(0xffffffffu, s3, 16);
            acc += fmaxf(s0 + b2f, 0.f) + fmaxf(s1 + b2f, 0.f)
                 + fmaxf(s2 + b2f, 0.f) + fmaxf(s3 + b2f, 0.f);
        }
        if (half == 0) out[node * C_ + c] = acc * (1.0f / K_);
    }
}

// ---------------------------------------------------------------------------
extern "C" void kernel_launch(void* const* d_in, const int* in_sizes, int n_in,
                              void* d_out, int out_size)
{
    const float* feats = (const float*)d_in[0];
    const float* adj   = (const float*)d_in[1];
    const float* w1    = (const float*)d_in[2];
    const float* b1    = (const float*)d_in[3];
    const float* g1    = (const float*)d_in[4];
    const float* be1   = (const float*)d_in[5];
    const float* mu1   = (const float*)d_in[6];
    const float* v1    = (const float*)d_in[7];
    const float* w2    = (const float*)d_in[8];
    const float* b2    = (const float*)d_in[9];
    const float* g2    = (const float*)d_in[10];
    const float* be2   = (const float*)d_in[11];
    const float* mu2   = (const float*)d_in[12];
    const float* v2    = (const float*)d_in[13];
    float* out = (float*)d_out;

    extract_f0_kernel<<<(B_ * N_ + 1023) / 1024, 1024>>>(feats);
    topk_kernel<<<B_ * N_, 256>>>(adj);
    edgeconv_kernel<<<(B_ * N_) / 16, 256>>>(feats, w1, b1, g1, be1, mu1, v1,
                                             w2, b2, g2, be2, mu2, v2, out);
}

// round 5
// speedup vs baseline: 1.1636x; 1.1636x over previous
#include <cuda_runtime.h>

#define B_ 16
#define N_ 1024
#define D_ 64
#define C_ 64
#define K_ 20
#define EPS_ 0.001f
#define PAIRS_ 4          // node-pairs per group; block = 2 groups * 4 pairs * 2 nodes = 16 nodes

// scratch (no cudaMalloc allowed)
__device__ int   g_nn_idx[B_ * N_ * K_];
__device__ float g_f0[B_ * N_];

// ---------------------------------------------------------------------------
// packed fp32x2 helpers (sm_103a FFMA2)
// ---------------------------------------------------------------------------
__device__ __forceinline__ unsigned long long pack2(float x, float y) {
    float2 f = make_float2(x, y);
    return *reinterpret_cast<unsigned long long*>(&f);
}
__device__ __forceinline__ float2 unpack2(unsigned long long u) {
    return *reinterpret_cast<float2*>(&u);
}
__device__ __forceinline__ unsigned long long ffma2(unsigned long long a,
                                                    unsigned long long b,
                                                    unsigned long long c) {
    unsigned long long d;
    asm("fma.rn.f32x2 %0, %1, %2, %3;" : "=l"(d) : "l"(a), "l"(b), "l"(c));
    return d;
}

// ---------------------------------------------------------------------------
// Kernel 0: densify f0 = feats[:,:,0]
// ---------------------------------------------------------------------------
__global__ void extract_f0_kernel(const float* __restrict__ feats) {
    int i = blockIdx.x * blockDim.x + threadIdx.x;
    if (i < B_ * N_) g_f0[i] = feats[(size_t)i * D_];
}

// ---------------------------------------------------------------------------
// Kernel 1: exact top-20 smallest of a[j] = adj[b,n,j]*|f0[b,j]-f0[b,n]|.
// Keys unique (index embedded); REDUX-based argmin; lowest-index tie-break
// matches jax.lax.top_k.
// ---------------------------------------------------------------------------
__global__ void topk_kernel(const float* __restrict__ adj) {
    const int row  = blockIdx.x;            // b*N + n
    const int b    = row >> 10;
    const int tid  = threadIdx.x;           // 256 threads
    const int lane = tid & 31;
    const int wid  = tid >> 5;              // 8 warps

    const float  f0n  = g_f0[row];
    const float* arow = adj + (size_t)row * N_;
    const float* f0b  = g_f0 + b * N_;

    unsigned long long key[4];
#pragma unroll
    for (int t = 0; t < 4; t++) {
        int j = tid + t * 256;
        float a = arow[j] * fabsf(f0b[j] - f0n);
        key[t] = ((unsigned long long)__float_as_uint(a) << 32) | (unsigned)j;
    }
#define CSWP(x, y) { unsigned long long lo = (x) < (y) ? (x) : (y); \
                     unsigned long long hi = (x) < (y) ? (y) : (x); (x) = lo; (y) = hi; }
    CSWP(key[0], key[1]); CSWP(key[2], key[3]);
    CSWP(key[0], key[2]); CSWP(key[1], key[3]);
    CSWP(key[1], key[2]);
#undef CSWP

    __shared__ unsigned long long cand[8][K_];

#pragma unroll 1
    for (int i = 0; i < K_; i++) {
        unsigned v = (unsigned)(key[0] >> 32);
        unsigned m = __reduce_min_sync(0xffffffffu, v);
        unsigned ic = (v == m) ? (unsigned)key[0] : 0xffffffffu;
        unsigned mi = __reduce_min_sync(0xffffffffu, ic);
        if (lane == 0) cand[wid][i] = ((unsigned long long)m << 32) | mi;
        if (v == m && (unsigned)key[0] == mi) {
            key[0] = key[1]; key[1] = key[2]; key[2] = key[3];
            key[3] = ~0ULL;
        }
    }
    __syncthreads();

    if (wid == 0) {
        int q = 0;
        const int out_base = row * K_;
#pragma unroll 1
        for (int i = 0; i < K_; i++) {
            unsigned long long myk = (lane < 8) ? cand[lane][q] : ~0ULL;
            unsigned v = (unsigned)(myk >> 32);
            unsigned m = __reduce_min_sync(0xffffffffu, v);
            unsigned ic = (v == m) ? (unsigned)myk : 0xffffffffu;
            unsigned mi = __reduce_min_sync(0xffffffffu, ic);
            if (lane == 0) g_nn_idx[out_base + i] = (int)mi;
            if (v == m && (unsigned)myk == mi) q++;
        }
    }
}

// ---------------------------------------------------------------------------
// Kernel 2: fused gather + MLP + mean. R3 structure (full reduction per
// thread, FFMA2 along d), but each 64-thread group processes TWO nodes per
// barrier interval -> 8 independent FFMA2 chains, 1 sync per node.
// dbuf is single-buffered: next pair's gather (register-prefetched during
// layer 1) is stored between the mid sync (dbuf dead after layer 1) and
// layer 2. Dynamic smem (58 KB).
// smem float layout: w1c[4096] | cf[2][2][64] | dbuf[2][2][20][64] | hbuf[2][2][20][64]
// ---------------------------------------------------------------------------
#define SM_W1C  0
#define SM_CF   4096
#define SM_DBUF (4096 + 256)
#define SM_HBUF (4096 + 256 + 5120)
#define SM_FLOATS (4096 + 256 + 5120 + 5120)

__global__ void __launch_bounds__(128, 2) edgeconv_kernel(
    const float* __restrict__ feats,
    const float* __restrict__ w1,  const float* __restrict__ b1,
    const float* __restrict__ g1,  const float* __restrict__ be1,
    const float* __restrict__ mu1, const float* __restrict__ v1,
    const float* __restrict__ w2,  const float* __restrict__ b2,
    const float* __restrict__ g2,  const float* __restrict__ be2,
    const float* __restrict__ mu2, const float* __restrict__ v2,
    float* __restrict__ out)
{
    extern __shared__ __align__(16) float sm[];
    float* w1c_s = sm + SM_W1C;

    const int tid = threadIdx.x;
    const int c   = tid & (C_ - 1);
    const int grp = tid >> 6;
    const int bbase = ((blockIdx.x * 16) >> 10) << 10;   // b*N (const per block)

    float* cfA = sm + SM_CF + (grp * 2 + 0) * C_;
    float* cfB = sm + SM_CF + (grp * 2 + 1) * C_;
    float* dA  = sm + SM_DBUF + (grp * 2 + 0) * (K_ * C_);
    float* dB  = sm + SM_DBUF + (grp * 2 + 1) * (K_ * C_);
    float* hA  = sm + SM_HBUF + (grp * 2 + 0) * (K_ * C_);
    float* hB  = sm + SM_HBUF + (grp * 2 + 1) * (K_ * C_);

    const float s1c = g1[c] * rsqrtf(v1[c] + EPS_);
    const float b1f = (b1[c] - mu1[c]) * s1c + be1[c];
    const float s2c = g2[c] * rsqrtf(v2[c] + EPS_);
    const float b2f = (b2[c] - mu2[c]) * s2c + be2[c];

    unsigned long long W1[D_ / 2];   // packed folded w1[64+2i..+1][c]
    unsigned long long W2[C_ / 2];   // packed folded w2[2i..+1][c]
#pragma unroll
    for (int i = 0; i < D_ / 2; i++)
        W1[i] = pack2(w1[(D_ + 2 * i) * C_ + c] * s1c,
                      w1[(D_ + 2 * i + 1) * C_ + c] * s1c);
#pragma unroll
    for (int i = 0; i < C_ / 2; i++)
        W2[i] = pack2(w2[(2 * i) * C_ + c] * s2c,
                      w2[(2 * i + 1) * C_ + c] * s2c);
    if (grp == 0) {
#pragma unroll
        for (int d = 0; d < D_; d++) w1c_s[d * C_ + c] = w1[d * C_ + c] * s1c;
    }

    // gather pair 0 directly
    {
        const int nA = blockIdx.x * 16 + grp * 2;
        const int nB = nA + 1;
        const float fA = feats[nA * D_ + c];
        const float fB = feats[nB * D_ + c];
        cfA[c] = fA;  cfB[c] = fB;
        const int* nnA = g_nn_idx + nA * K_;
        const int* nnB = g_nn_idx + nB * K_;
#pragma unroll
        for (int k = 0; k < K_; k++) {
            dA[k * C_ + c] = feats[(bbase + nnA[k]) * D_ + c] - fA;
            dB[k * C_ + c] = feats[(bbase + nnB[k]) * D_ + c] - fB;
        }
    }

#pragma unroll 1
    for (int i = 0; i < PAIRS_; i++) {
        const int nodeA = blockIdx.x * 16 + i * 4 + grp * 2;
        const int nodeB = nodeA + 1;
        __syncthreads();   // dbuf/cf for this pair ready; prev hbuf reads done

        // ---- prefetch next pair into registers (consumed after mid sync)
        float preA[K_], preB[K_];
        float fAn = 0.f, fBn = 0.f;
        if (i < PAIRS_ - 1) {
            const int mA = nodeA + 4, mB = nodeB + 4;
            const int* nnA = g_nn_idx + mA * K_;
            const int* nnB = g_nn_idx + mB * K_;
            fAn = feats[mA * D_ + c];
            fBn = feats[mB * D_ + c];
#pragma unroll
            for (int k = 0; k < K_; k++) {
                preA[k] = feats[(bbase + nnA[k]) * D_ + c];
                preB[k] = feats[(bbase + nnB[k]) * D_ + c];
            }
        }

        // ---- center contributions (both nodes)
        float ca0 = b1f, ca1 = 0.f, cb0 = b1f, cb1 = 0.f;
#pragma unroll
        for (int d = 0; d < D_; d += 2) {
            float2 va = *(const float2*)&cfA[d];
            float2 vb = *(const float2*)&cfB[d];
            ca0 += va.x * w1c_s[d * C_ + c];
            ca1 += va.y * w1c_s[(d + 1) * C_ + c];
            cb0 += vb.x * w1c_s[d * C_ + c];
            cb1 += vb.y * w1c_s[(d + 1) * C_ + c];
        }
        const unsigned long long pcA = pack2(ca0 + ca1, 0.f);
        const unsigned long long pcB = pack2(cb0 + cb1, 0.f);

        // ---- layer 1: both nodes, k-tiled 4 -> 8 independent chains
#pragma unroll 1
        for (int t = 0; t < K_; t += 4) {
            unsigned long long A0 = pcA, A1 = pcA, A2 = pcA, A3 = pcA;
            unsigned long long B0 = pcB, B1 = pcB, B2 = pcB, B3 = pcB;
            const float* ra = &dA[t * C_];
            const float* rb = &dB[t * C_];
#pragma unroll
            for (int d = 0; d < D_; d += 4) {
                const int w = d >> 1;
                ulonglong2 qa0 = *(const ulonglong2*)&ra[0 * C_ + d];
                ulonglong2 qa1 = *(const ulonglong2*)&ra[1 * C_ + d];
                ulonglong2 qa2 = *(const ulonglong2*)&ra[2 * C_ + d];
                ulonglong2 qa3 = *(const ulonglong2*)&ra[3 * C_ + d];
                ulonglong2 qb0 = *(const ulonglong2*)&rb[0 * C_ + d];
                ulonglong2 qb1 = *(const ulonglong2*)&rb[1 * C_ + d];
                ulonglong2 qb2 = *(const ulonglong2*)&rb[2 * C_ + d];
                ulonglong2 qb3 = *(const ulonglong2*)&rb[3 * C_ + d];
                A0 = ffma2(qa0.x, W1[w], A0);  A0 = ffma2(qa0.y, W1[w + 1], A0);
                A1 = ffma2(qa1.x, W1[w], A1);  A1 = ffma2(qa1.y, W1[w + 1], A1);
                A2 = ffma2(qa2.x, W1[w], A2);  A2 = ffma2(qa2.y, W1[w + 1], A2);
                A3 = ffma2(qa3.x, W1[w], A3);  A3 = ffma2(qa3.y, W1[w + 1], A3);
                B0 = ffma2(qb0.x, W1[w], B0);  B0 = ffma2(qb0.y, W1[w + 1], B0);
                B1 = ffma2(qb1.x, W1[w], B1);  B1 = ffma2(qb1.y, W1[w + 1], B1);
                B2 = ffma2(qb2.x, W1[w], B2);  B2 = ffma2(qb2.y, W1[w + 1], B2);
                B3 = ffma2(qb3.x, W1[w], B3);  B3 = ffma2(qb3.y, W1[w + 1], B3);
            }
            float2 a0 = unpack2(A0), a1 = unpack2(A1), a2 = unpack2(A2), a3 = unpack2(A3);
            float2 b0 = unpack2(B0), b1_ = unpack2(B1), b2_ = unpack2(B2), b3 = unpack2(B3);
            hA[(t + 0) * C_ + c] = fmaxf(a0.x + a0.y, 0.f);
            hA[(t + 1) * C_ + c] = fmaxf(a1.x + a1.y, 0.f);
            hA[(t + 2) * C_ + c] = fmaxf(a2.x + a2.y, 0.f);
            hA[(t + 3) * C_ + c] = fmaxf(a3.x + a3.y, 0.f);
            hB[(t + 0) * C_ + c] = fmaxf(b0.x + b0.y, 0.f);
            hB[(t + 1) * C_ + c] = fmaxf(b1_.x + b1_.y, 0.f);
            hB[(t + 2) * C_ + c] = fmaxf(b2_.x + b2_.y, 0.f);
            hB[(t + 3) * C_ + c] = fmaxf(b3.x + b3.y, 0.f);
        }
        __syncthreads();   // hbuf ready; dbuf dead (all layer-1 reads done)

        // ---- store prefetched gather into (now dead) dbuf/cf
        if (i < PAIRS_ - 1) {
            cfA[c] = fAn;  cfB[c] = fBn;
#pragma unroll
            for (int k = 0; k < K_; k++) {
                dA[k * C_ + c] = preA[k] - fAn;
                dB[k * C_ + c] = preB[k] - fBn;
            }
        }

        // ---- layer 2: both nodes, k-tiled 4; mean accumulate
        const unsigned long long pb = pack2(b2f, 0.f);
        float accA = 0.f, accB = 0.f;
#pragma unroll 1
        for (int t = 0; t < K_; t += 4) {
            unsigned long long A0 = pb, A1 = pb, A2 = pb, A3 = pb;
            unsigned long long B0 = pb, B1 = pb, B2 = pb, B3 = pb;
            const float* ra = &hA[t * C_];
            const float* rb = &hB[t * C_];
#pragma unroll
            for (int e = 0; e < C_; e += 4) {
                const int w = e >> 1;
                ulonglong2 qa0 = *(const ulonglong2*)&ra[0 * C_ + e];
                ulonglong2 qa1 = *(const ulonglong2*)&ra[1 * C_ + e];
                ulonglong2 qa2 = *(const ulonglong2*)&ra[2 * C_ + e];
                ulonglong2 qa3 = *(const ulonglong2*)&ra[3 * C_ + e];
                ulonglong2 qb0 = *(const ulonglong2*)&rb[0 * C_ + e];
                ulonglong2 qb1 = *(const ulonglong2*)&rb[1 * C_ + e];
                ulonglong2 qb2 = *(const ulonglong2*)&rb[2 * C_ + e];
                ulonglong2 qb3 = *(const ulonglong2*)&rb[3 * C_ + e];
                A0 = ffma2(qa0.x, W2[w], A0);  A0 = ffma2(qa0.y, W2[w + 1], A0);
                A1 = ffma2(qa1.x, W2[w], A1);  A1 = ffma2(qa1.y, W2[w + 1], A1);
                A2 = ffma2(qa2.x, W2[w], A2);  A2 = ffma2(qa2.y, W2[w + 1], A2);
                A3 = ffma2(qa3.x, W2[w], A3);  A3 = ffma2(qa3.y, W2[w + 1], A3);
                B0 = ffma2(qb0.x, W2[w], B0);  B0 = ffma2(qb0.y, W2[w + 1], B0);
                B1 = ffma2(qb1.x, W2[w], B1);  B1 = ffma2(qb1.y, W2[w + 1], B1);
                B2 = ffma2(qb2.x, W2[w], B2);  B2 = ffma2(qb2.y, W2[w + 1], B2);
                B3 = ffma2(qb3.x, W2[w], B3);  B3 = ffma2(qb3.y, W2[w + 1], B3);
            }
            float2 a0 = unpack2(A0), a1 = unpack2(A1), a2 = unpack2(A2), a3 = unpack2(A3);
            float2 b0 = unpack2(B0), b1_ = unpack2(B1), b2_ = unpack2(B2), b3 = unpack2(B3);
            accA += fmaxf(a0.x + a0.y, 0.f) + fmaxf(a1.x + a1.y, 0.f)
                  + fmaxf(a2.x + a2.y, 0.f) + fmaxf(a3.x + a3.y, 0.f);
            accB += fmaxf(b0.x + b0.y, 0.f) + fmaxf(b1_.x + b1_.y, 0.f)
                  + fmaxf(b2_.x + b2_.y, 0.f) + fmaxf(b3.x + b3.y, 0.f);
        }
        out[nodeA * C_ + c] = accA * (1.0f / K_);
        out[nodeB * C_ + c] = accB * (1.0f / K_);
    }
}

// ---------------------------------------------------------------------------
extern "C" void kernel_launch(void* const* d_in, const int* in_sizes, int n_in,
                              void* d_out, int out_size)
{
    const float* feats = (const float*)d_in[0];
    const float* adj   = (const float*)d_in[1];
    const float* w1    = (const float*)d_in[2];
    const float* b1    = (const float*)d_in[3];
    const float* g1    = (const float*)d_in[4];
    const float* be1   = (const float*)d_in[5];
    const float* mu1   = (const float*)d_in[6];
    const float* v1    = (const float*)d_in[7];
    const float* w2    = (const float*)d_in[8];
    const float* b2    = (const float*)d_in[9];
    const float* g2    = (const float*)d_in[10];
    const float* be2   = (const float*)d_in[11];
    const float* mu2   = (const float*)d_in[12];
    const float* v2    = (const float*)d_in[13];
    float* out = (float*)d_out;

    static int smem_set = 0;
    if (!smem_set) {
        cudaFuncSetAttribute(edgeconv_kernel,
                             cudaFuncAttributeMaxDynamicSharedMemorySize,
                             SM_FLOATS * (int)sizeof(float));
        smem_set = 1;
    }

    extract_f0_kernel<<<(B_ * N_ + 1023) / 1024, 1024>>>(feats);
    topk_kernel<<<B_ * N_, 256>>>(adj);
    edgeconv_kernel<<<(B_ * N_) / 16, 128, SM_FLOATS * (int)sizeof(float)>>>(
        feats, w1, b1, g1, be1, mu1, v1, w2, b2, g2, be2, mu2, v2, out);
}